// round 9
// baseline (speedup 1.0000x reference)
#include <cuda_runtime.h>
#include <stdint.h>

typedef unsigned long long u64;
#define FULLMASK 0xffffffffu

static constexpr int B     = 2;
static constexpr int CLS   = 4;
static constexpr int NPTS  = 32;
static constexpr int N_OUT = CLS * NPTS;      // 128
static constexpr int SVOX  = 1 << 21;         // 128^3
static constexpr int S1B   = 128;             // stage1 chunks per (b,c)
static constexpr int S1N   = 4096;            // elements per stage1 chunk
static constexpr int CAP   = S1B * S1N;       // 524288 per (b,c)
static constexpr int MIDK  = 16;              // kept per stage1 chunk
static constexpr int MIDN  = S1B * MIDK;      // 2048

// ---------------- static device scratch (no allocations) -----------------
__device__ u64          g_cand[B * CLS][CAP]; // (f32 s-bits << 21) | voxel idx
__device__ unsigned int g_cnt[B * CLS];
__device__ u64          g_mid[B * CLS][MIDN];

// ---------------- FMA-only exp (x <= 0), rel err ~1e-7, no MUFU ----------
__device__ __forceinline__ float fexp(float x) {
    float t = x * 1.4426950408889634f;
    float n = rintf(t);
    float r = fmaf(n, -0.69314718246459960938f, x);
    r       = fmaf(n,  1.90821492233381634e-9f, r);
    float p = 1.3888889e-3f;
    p = fmaf(p, r, 8.3333333e-3f);
    p = fmaf(p, r, 4.1666667e-2f);
    p = fmaf(p, r, 1.6666667e-1f);
    p = fmaf(p, r, 0.5f);
    p = fmaf(p, r, 1.0f);
    p = fmaf(p, r, 1.0f);                      // fexp(0) == 1 exactly
    int e = (int)n;
    e = e < -126 ? -126 : (e > 126 ? 126 : e);
    return p * __int_as_float((e + 127) << 23);
}

// ---------------- kernel 0: zero counters --------------------------------
__global__ void init_kernel() {
    int t = threadIdx.x;
    if (t < B * CLS) g_cnt[t] = 0u;
}

// ---------------- kernel 1: full scan, append ALL candidates -------------
// grid = B*(SVOX/1024) = 4096 blocks, 256 threads, 4 voxels/thread
__global__ __launch_bounds__(256) void filter_kernel(const float* __restrict__ logits) {
    const int tid = threadIdx.x;
    const int b   = blockIdx.x >> 11;
    const unsigned v0 = (unsigned)(blockIdx.x & 2047) * 1024u + (unsigned)tid * 4u;

    const float4* p4 = (const float4*)(logits + (size_t)b * CLS * SVOX);
    float4 x0 = p4[(0u * SVOX + v0) >> 2];
    float4 x1 = p4[(1u * SVOX + v0) >> 2];
    float4 x2 = p4[(2u * SVOX + v0) >> 2];
    float4 x3 = p4[(3u * SVOX + v0) >> 2];

    float c0[4] = {x0.x, x0.y, x0.z, x0.w};
    float c1[4] = {x1.x, x1.y, x1.z, x1.w};
    float c2[4] = {x2.x, x2.y, x2.z, x2.w};
    float c3[4] = {x3.x, x3.y, x3.z, x3.w};

#pragma unroll
    for (int i = 0; i < 4; i++) {
        float a = c0[i], bb = c1[i], cc = c2[i], dd = c3[i];
        float m = a; int am = 0;
        if (bb > m) { m = bb; am = 1; }
        if (cc > m) { m = cc; am = 2; }
        if (dd > m) { m = dd; am = 3; }
        // s = sum_j e^{x_j - m} in [1,4); prob_argmax = 1/s > 0.5 <=> s < 2
        float s = fexp(a - m) + fexp(bb - m) + fexp(cc - m) + fexp(dd - m);
        if (s < 2.0f) {
            int g = b * CLS + am;
            u64 key = ((u64)__float_as_uint(s) << 21) | (u64)(v0 + (unsigned)i);
            unsigned pos = atomicAdd(&g_cnt[g], 1u);
            if (pos < (unsigned)CAP) g_cand[g][pos] = key;
        }
    }
}

// ---------------- shared-memory bitonic sort (ascending, 256 threads) ----
template <int N>
__device__ void bitonic_sort(u64* sh, int tid) {
#pragma unroll 1
    for (int k = 2; k <= N; k <<= 1) {
#pragma unroll 1
        for (int j = k >> 1; j > 0; j >>= 1) {
            __syncthreads();
            for (int i = tid; i < N; i += 256) {
                int p = i ^ j;
                if (p > i) {
                    u64 a = sh[i], b = sh[p];
                    bool asc = (i & k) == 0;
                    if ((a > b) == asc) { sh[i] = b; sh[p] = a; }
                }
            }
        }
    }
    __syncthreads();
}

// ---------------- kernel 2: per-4096-chunk local top-16 ------------------
// grid = (S1B, B*CLS)
__global__ __launch_bounds__(256) void stage1_kernel() {
    __shared__ u64 sh[S1N];                    // 32 KB
    const int g   = blockIdx.y;
    const int jb  = blockIdx.x;
    const int tid = threadIdx.x;

    unsigned cnt = g_cnt[g]; if (cnt > (unsigned)CAP) cnt = CAP;
    unsigned base = (unsigned)jb * S1N;
    if (base >= cnt) {                         // inactive chunk: sentinels
        if (tid < MIDK) g_mid[g][jb * MIDK + tid] = ~0ull;
        return;
    }
#pragma unroll
    for (int r = 0; r < S1N / 256; r++) {
        unsigned i = base + (unsigned)tid + (unsigned)r * 256u;
        sh[tid + r * 256] = (i < cnt) ? g_cand[g][i] : ~0ull;
    }
    bitonic_sort<S1N>(sh, tid);
    if (tid < MIDK) g_mid[g][jb * MIDK + tid] = sh[tid];
}

// ---------------- double-precision exact key for final ranking -----------
__device__ __forceinline__ u64 dkey(u64 fkey, const float* __restrict__ base) {
    if (fkey == ~0ull) return ~0ull;
    unsigned idx = (unsigned)(fkey & 0x1FFFFFu);
    double a  = (double)base[idx];
    double x1 = (double)base[SVOX + idx];
    double x2 = (double)base[2u * SVOX + idx];
    double x3 = (double)base[3u * SVOX + idx];
    double m  = fmax(fmax(a, x1), fmax(x2, x3));
    double sd = exp(a - m) + exp(x1 - m) + exp(x2 - m) + exp(x3 - m);  // >= 1
    u64 diff = (u64)__double_as_longlong(sd) - 0x3FF0000000000000ull;
    if (diff > 0xFFFFFFFFFFFFFull) diff = 0xFFFFFFFFFFFFFull;
    return ((diff >> 9) << 21) | (u64)idx;     // asc = best; tie -> smaller idx
}

// ---------------- kernel 3: merge, exact top-32, write FLOAT output ------
// grid = B*CLS blocks; block g handles class c = g&3 of batch b = g>>2
__global__ __launch_bounds__(256) void stage2_kernel(const float* __restrict__ logits,
                                                     float* __restrict__ out,
                                                     int out_size) {
    __shared__ u64 sh[MIDN];                   // 16 KB
    const int g   = blockIdx.x;
    const int tid = threadIdx.x;
    const int b   = g >> 2, c = g & 3;
    const int w   = (c + 3) & 3;               // position in visit order [1,2,3,0]
    float* crd = out;                           // coords [B][128][3] at offset 0
    const bool has_lab = out_size >= B * N_OUT * 3 + B * N_OUT;
    float* lab = out + (out_size - B * N_OUT); // labels [B][128] at tail

    int off = 0;
    for (int o = 0; o < w; o++) {
        int t = (int)g_cnt[b * CLS + ((o + 1) & 3)];
        off += t < NPTS ? t : NPTS;
    }
    int cnt = (int)g_cnt[g]; if (cnt > CAP) cnt = CAP;
    int k = cnt < NPTS ? cnt : NPTS;

    if (w == 3) {                              // last class fills padding tail
        int tot = off + k;
        for (int i = tot + tid; i < N_OUT; i += 256) {
            if (has_lab) lab[b * N_OUT + i] = -1.0f;
            crd[(b * N_OUT + i) * 3 + 0] = 0.0f;
            crd[(b * N_OUT + i) * 3 + 1] = 0.0f;
            crd[(b * N_OUT + i) * 3 + 2] = 0.0f;
        }
    }

#pragma unroll
    for (int r = 0; r < MIDN / 256; r++) {
        int j = tid + r * 256;
        sh[j] = g_mid[g][j];
    }
    bitonic_sort<MIDN>(sh, tid);

    if (tid < 32) {                            // warp 0: exact re-rank of top 48
        const float* base = logits + (size_t)b * CLS * SVOX;
        u64 k0 = dkey(sh[tid], base);
        u64 k1 = (tid < 16) ? dkey(sh[32 + tid], base) : ~0ull;

        for (int r = 0; r < k; r++) {
            u64 mn = k0 < k1 ? k0 : k1;
            for (int o = 16; o; o >>= 1) {
                u64 t = __shfl_xor_sync(FULLMASK, mn, o);
                if (t < mn) mn = t;
            }
            if (mn == ~0ull) break;
            if (k0 == mn) k0 = ~0ull; else if (k1 == mn) k1 = ~0ull;
            if (tid == 0) {
                int idx  = (int)(mn & 0x1FFFFFull);
                int slot = off + r;
                if (has_lab) lab[b * N_OUT + slot] = (float)c;
                crd[(b * N_OUT + slot) * 3 + 0] = (float)(idx >> 14);
                crd[(b * N_OUT + slot) * 3 + 1] = (float)((idx >> 7) & 127);
                crd[(b * N_OUT + slot) * 3 + 2] = (float)(idx & 127);
            }
        }
    }
}

// ---------------- launch ---------------------------------------------------
extern "C" void kernel_launch(void* const* d_in, const int* in_sizes, int n_in,
                              void* d_out, int out_size) {
    // select the logits input by element count (robust to extra inputs)
    const long long want = (long long)B * CLS * SVOX;   // 16,777,216
    int li = 0;
    for (int i = 0; i < n_in; i++)
        if ((long long)in_sizes[i] == want) { li = i; break; }
    if ((long long)in_sizes[li] != want)
        for (int i = 1; i < n_in; i++)
            if (in_sizes[i] > in_sizes[li]) li = i;

    const float* logits = (const float*)d_in[li];
    float* out = (float*)d_out;

    init_kernel<<<1, 32>>>();
    filter_kernel<<<B * (SVOX / 1024), 256>>>(logits);
    stage1_kernel<<<dim3(S1B, B * CLS), 256>>>();
    stage2_kernel<<<B * CLS, 256>>>(logits, out, out_size);
}

// round 11
// speedup vs baseline: 7.0690x; 7.0690x over previous
#include <cuda_runtime.h>
#include <stdint.h>

typedef unsigned long long u64;
#define FULLMASK 0xffffffffu

static constexpr int B     = 2;
static constexpr int CLS   = 4;
static constexpr int NPTS  = 32;
static constexpr int N_OUT = CLS * NPTS;      // 128
static constexpr int SVOX  = 1 << 21;         // 128^3
static constexpr int SCAP  = 8192;            // sample buffer per (b,c)
static constexpr int CAP   = 16384;           // survivor buffer per (b,c)
static constexpr int RANK  = 40;              // sample order stat (>= NPTS)
static constexpr int TOPK  = 48;              // exact re-rank width
static constexpr int SHK   = 6144;            // survivors staged in shared (48 KB)

// ---------------- static device scratch (no allocations) -----------------
__device__ float    g_samp[B * CLS][SCAP];
__device__ unsigned g_scnt[B * CLS];
__device__ float    g_cut[B * CLS];
__device__ float    g_td[B * CLS];
__device__ u64      g_surv[B * CLS][CAP];
__device__ unsigned g_cnt[B * CLS];

// ---------------- FMA-only exp (x <= 0), rel err ~1e-7, no MUFU ----------
__device__ __forceinline__ float fexp(float x) {
    float t = x * 1.4426950408889634f;
    float n = rintf(t);
    float r = fmaf(n, -0.69314718246459960938f, x);
    r       = fmaf(n,  1.90821492233381634e-9f, r);
    float p = 1.3888889e-3f;
    p = fmaf(p, r, 8.3333333e-3f);
    p = fmaf(p, r, 4.1666667e-2f);
    p = fmaf(p, r, 1.6666667e-1f);
    p = fmaf(p, r, 0.5f);
    p = fmaf(p, r, 1.0f);
    p = fmaf(p, r, 1.0f);                      // fexp(0) == 1 exactly
    int e = (int)n;
    e = e < -126 ? -126 : (e > 126 ? 126 : e);
    return p * __int_as_float((e + 127) << 23);
}

// bit-identical in sample and scan slow path (survivor guarantee depends on it)
__device__ __forceinline__ float s_of(float a, float b, float c, float d,
                                      float m) {
    return fexp(a - m) + fexp(b - m) + fexp(c - m) + fexp(d - m);   // [1,4)
}
__device__ __forceinline__ int argmax4(float a, float b, float c, float d,
                                       float& m) {
    m = a; int am = 0;
    if (b > m) { m = b; am = 1; }
    if (c > m) { m = c; am = 2; }
    if (d > m) { m = d; am = 3; }
    return am;
}

// ---------------- kernel 0: zero counters --------------------------------
__global__ void init_kernel() {
    int t = threadIdx.x;
    if (t < B * CLS) { g_scnt[t] = 0u; g_cnt[t] = 0u; }
}

// ---------------- kernel 1: 1/64 sampling (exact fexp s) -----------------
// grid (SVOX/8192 = 256, B), 128 threads: first 128 voxels of each 8192-run
__global__ void sample_kernel(const float* __restrict__ logits) {
    int b = blockIdx.y;
    unsigned v = blockIdx.x * 8192u + threadIdx.x;
    const float* base = logits + (size_t)b * CLS * SVOX;
    float a  = base[v];
    float x1 = base[SVOX + v];
    float x2 = base[2u * SVOX + v];
    float x3 = base[3u * SVOX + v];
    float m; int am = argmax4(a, x1, x2, x3, m);
    float s = s_of(a, x1, x2, x3, m);
    if (s < 2.0f) {                            // prob_argmax = 1/s > 0.5
        int g = b * CLS + am;
        unsigned p = atomicAdd(&g_scnt[g], 1u);
        if (p < SCAP) g_samp[g][p] = s;
    }
}

// ---------------- kernel 2: per-(b,c) cutoff = RANK-th smallest s --------
// grid = B*CLS blocks, 256 threads
__global__ __launch_bounds__(256) void cutoff_kernel() {
    __shared__ float sv[SCAP];                 // 32 KB
    __shared__ float red[8];
    __shared__ float bc;
    const int g = blockIdx.x, tid = threadIdx.x;
    unsigned mc = g_scnt[g]; if (mc > SCAP) mc = SCAP;
    for (unsigned i = tid; i < mc; i += 256) sv[i] = g_samp[g][i];
    __syncthreads();

    float cut = 2.0f;                          // sentinel: keep everything
    if (mc >= (unsigned)RANK) {
        float prev = 0.0f;
        for (int r = 0; r < RANK; r++) {
            float loc = 3.0f;
            for (unsigned i = tid; i < mc; i += 256) {
                float vv = sv[i];
                if (vv > prev && vv < loc) loc = vv;
            }
            for (int o = 16; o; o >>= 1) {
                float t = __shfl_xor_sync(FULLMASK, loc, o);
                if (t < loc) loc = t;
            }
            if ((tid & 31) == 0) red[tid >> 5] = loc;
            __syncthreads();
            if (tid == 0) {
                float mn = red[0];
                for (int j = 1; j < 8; j++) if (red[j] < mn) mn = red[j];
                bc = mn;
            }
            __syncthreads();
            float cur = bc;
            __syncthreads();
            if (cur >= 2.5f) break;            // ran out of distinct values
            prev = cur;
        }
        cut = prev;
    }
    if (tid == 0) {
        g_cut[g] = cut;
        float eps = cut - 1.0f;
        if (eps < 1e-30f) eps = 1e-30f;
        g_td[g] = -logf(eps) - 0.01f;          // (max-sec) >= td necessary for s<=cut
    }
}

// ---------------- kernel 3: exp-free full scan (HBM-bound) ----------------
// grid = B*(SVOX/1024) = 4096 blocks, 256 threads, 4 voxels/thread
__global__ __launch_bounds__(256) void scan_kernel(const float* __restrict__ logits) {
    const int tid = threadIdx.x;
    const int b   = blockIdx.x >> 11;
    const unsigned v0 = (unsigned)(blockIdx.x & 2047) * 1024u + (unsigned)tid * 4u;

    const float td = fminf(fminf(g_td[b * CLS],     g_td[b * CLS + 1]),
                           fminf(g_td[b * CLS + 2], g_td[b * CLS + 3]));

    const float4* p4 = (const float4*)(logits + (size_t)b * CLS * SVOX);
    float4 x0 = p4[(0u * SVOX + v0) >> 2];
    float4 x1 = p4[(1u * SVOX + v0) >> 2];
    float4 x2 = p4[(2u * SVOX + v0) >> 2];
    float4 x3 = p4[(3u * SVOX + v0) >> 2];

    float c0[4] = {x0.x, x0.y, x0.z, x0.w};
    float c1[4] = {x1.x, x1.y, x1.z, x1.w};
    float c2[4] = {x2.x, x2.y, x2.z, x2.w};
    float c3[4] = {x3.x, x3.y, x3.z, x3.w};

#pragma unroll
    for (int i = 0; i < 4; i++) {
        float a = c0[i], bb = c1[i], cc = c2[i], dd = c3[i];
        // top-2 of 4 via min/max tree (no exp)
        float s1 = fmaxf(a, bb),  s2 = fminf(a, bb);
        float t1 = fmaxf(cc, dd), t2 = fminf(cc, dd);
        float hi  = fmaxf(s1, t1);
        float sec = fmaxf(fminf(s1, t1), fmaxf(s2, t2));
        if (hi - sec >= td) {                   // rare slow path (~0.1%)
            float m; int am = argmax4(a, bb, cc, dd, m);
            float s = s_of(a, bb, cc, dd, m);
            int g = b * CLS + am;
            if (s < 2.0f && s <= g_cut[g]) {
                u64 key = ((u64)__float_as_uint(s) << 21) | (u64)(v0 + (unsigned)i);
                unsigned pos = atomicAdd(&g_cnt[g], 1u);
                if (pos < (unsigned)CAP) g_surv[g][pos] = key;
            }
        }
    }
}

// ---------------- double-precision exact key for final ranking -----------
__device__ __forceinline__ u64 dkey(u64 fkey, const float* __restrict__ base) {
    if (fkey == ~0ull) return ~0ull;
    unsigned idx = (unsigned)(fkey & 0x1FFFFFu);
    double a  = (double)base[idx];
    double x1 = (double)base[SVOX + idx];
    double x2 = (double)base[2u * SVOX + idx];
    double x3 = (double)base[3u * SVOX + idx];
    double m  = fmax(fmax(a, x1), fmax(x2, x3));
    double sd = exp(a - m) + exp(x1 - m) + exp(x2 - m) + exp(x3 - m);
    u64 diff = (u64)__double_as_longlong(sd) - 0x3FF0000000000000ull;
    if (diff > 0xFFFFFFFFFFFFFull) diff = 0xFFFFFFFFFFFFFull;
    return ((diff >> 9) << 21) | (u64)idx;     // asc = best; tie -> smaller idx
}

// ---------------- kernel 4: top-48 extract + exact top-32 + output -------
// grid = B*CLS blocks, 256 threads, static shared only (48 KB + eps)
__global__ __launch_bounds__(256) void final_kernel(const float* __restrict__ logits,
                                                    float* __restrict__ out,
                                                    int out_size) {
    __shared__ u64 sk[SHK];                    // 48 KB survivor stage
    __shared__ u64 s_top[TOPK];
    __shared__ u64 red[8];
    __shared__ u64 bc;
    const int g = blockIdx.x, tid = threadIdx.x;
    const int b = g >> 2, c = g & 3;
    const int w = (c + 3) & 3;                 // position in visit order [1,2,3,0]
    float* crd = out;                           // coords [B][128][3]
    const bool has_lab = out_size >= B * N_OUT * 4;
    float* lab = out + (out_size - B * N_OUT); // labels [B][128] at tail

    int cnt = (int)g_cnt[g];
    int m = cnt > CAP ? CAP : cnt;
    int k = cnt < NPTS ? cnt : NPTS; if (k > m) k = m;
    int off = 0;
    for (int o = 0; o < w; o++) {
        int t = (int)g_cnt[b * CLS + ((o + 1) & 3)];
        off += t < NPTS ? t : NPTS;
    }
    if (w == 3) {                              // last class fills padding tail
        int tot = off + k;
        for (int i = tot + tid; i < N_OUT; i += 256) {
            if (has_lab) lab[b * N_OUT + i] = -1.0f;
            crd[(b * N_OUT + i) * 3 + 0] = 0.0f;
            crd[(b * N_OUT + i) * 3 + 1] = 0.0f;
            crd[(b * N_OUT + i) * 3 + 2] = 0.0f;
        }
    }

    const int msh = m < SHK ? m : SHK;         // staged part
    for (int i = tid; i < msh; i += 256) sk[i] = g_surv[g][i];
    __syncthreads();

    // block-wide extraction of TOPK smallest f32-keys (shared + global tail)
    u64 prev = 0; int found = 0;
    for (int r = 0; r < TOPK; r++) {
        u64 loc = ~0ull;
        for (int i = tid; i < msh; i += 256) {
            u64 kk = sk[i];
            if (kk > prev && kk < loc) loc = kk;
        }
        for (int i = SHK + tid; i < m; i += 256) {     // overflow tail (rare)
            u64 kk = g_surv[g][i];
            if (kk > prev && kk < loc) loc = kk;
        }
        for (int o = 16; o; o >>= 1) {
            u64 t = __shfl_xor_sync(FULLMASK, loc, o);
            if (t < loc) loc = t;
        }
        if ((tid & 31) == 0) red[tid >> 5] = loc;
        __syncthreads();
        if (tid == 0) {
            u64 mn = red[0];
            for (int j = 1; j < 8; j++) if (red[j] < mn) mn = red[j];
            bc = mn; s_top[r] = mn;
        }
        __syncthreads();
        prev = bc;
        __syncthreads();
        if (prev == ~0ull) break;
        found = r + 1;
    }
    if (tid == 0)
        for (int r = found; r < TOPK; r++) s_top[r] = ~0ull;
    __syncthreads();

    if (tid < 32) {                            // warp 0: exact re-rank of top-48
        const float* base = logits + (size_t)b * CLS * SVOX;
        u64 k0 = dkey(s_top[tid], base);
        u64 k1 = (tid < 16) ? dkey(s_top[32 + tid], base) : ~0ull;
        for (int r = 0; r < k; r++) {
            u64 mn = k0 < k1 ? k0 : k1;
            for (int o = 16; o; o >>= 1) {
                u64 t = __shfl_xor_sync(FULLMASK, mn, o);
                if (t < mn) mn = t;
            }
            if (mn == ~0ull) break;
            if (k0 == mn) k0 = ~0ull; else if (k1 == mn) k1 = ~0ull;
            if (tid == 0) {
                int idx  = (int)(mn & 0x1FFFFFull);
                int slot = off + r;
                if (has_lab) lab[b * N_OUT + slot] = (float)c;
                crd[(b * N_OUT + slot) * 3 + 0] = (float)(idx >> 14);
                crd[(b * N_OUT + slot) * 3 + 1] = (float)((idx >> 7) & 127);
                crd[(b * N_OUT + slot) * 3 + 2] = (float)(idx & 127);
            }
        }
    }
}

// ---------------- launch (kernel launches ONLY — no other CUDA APIs) ------
extern "C" void kernel_launch(void* const* d_in, const int* in_sizes, int n_in,
                              void* d_out, int out_size) {
    const long long want = (long long)B * CLS * SVOX;   // 16,777,216
    int li = 0;
    for (int i = 0; i < n_in; i++)
        if ((long long)in_sizes[i] == want) { li = i; break; }
    if ((long long)in_sizes[li] != want)
        for (int i = 1; i < n_in; i++)
            if (in_sizes[i] > in_sizes[li]) li = i;

    const float* logits = (const float*)d_in[li];
    float* out = (float*)d_out;

    init_kernel<<<1, 32>>>();
    sample_kernel<<<dim3(SVOX / 8192, B), 128>>>(logits);
    cutoff_kernel<<<B * CLS, 256>>>();
    scan_kernel<<<B * (SVOX / 1024), 256>>>(logits);
    final_kernel<<<B * CLS, 256>>>(logits, out, out_size);
}

// round 12
// speedup vs baseline: 10.4546x; 1.4789x over previous
#include <cuda_runtime.h>
#include <stdint.h>

typedef unsigned long long u64;
#define FULLMASK 0xffffffffu

static constexpr int B      = 2;
static constexpr int CLS    = 4;
static constexpr int NPTS   = 32;
static constexpr int N_OUT  = CLS * NPTS;     // 128
static constexpr int SVOX   = 1 << 21;        // 128^3
static constexpr int SCAP   = 8192;           // sample buffer per (b,c)
static constexpr int CAP    = 16384;          // survivor buffer per (b,c)
static constexpr int RANK   = 40;             // sample order stat (>= NPTS)
static constexpr int TOPK   = 48;             // exact re-rank width
static constexpr int COLCAP = 2048;           // final collect capacity

// ---------------- static device scratch (no allocations) -----------------
__device__ float    g_samp[B * CLS][SCAP];
__device__ unsigned g_scnt[B * CLS];
__device__ float    g_cut[B * CLS];
__device__ float    g_td[B * CLS];
__device__ u64      g_surv[B * CLS][CAP];
__device__ unsigned g_cnt[B * CLS];

// ---------------- FMA-only exp (x <= 0), rel err ~1e-7, no MUFU ----------
__device__ __forceinline__ float fexp(float x) {
    float t = x * 1.4426950408889634f;
    float n = rintf(t);
    float r = fmaf(n, -0.69314718246459960938f, x);
    r       = fmaf(n,  1.90821492233381634e-9f, r);
    float p = 1.3888889e-3f;
    p = fmaf(p, r, 8.3333333e-3f);
    p = fmaf(p, r, 4.1666667e-2f);
    p = fmaf(p, r, 1.6666667e-1f);
    p = fmaf(p, r, 0.5f);
    p = fmaf(p, r, 1.0f);
    p = fmaf(p, r, 1.0f);                      // fexp(0) == 1 exactly
    int e = (int)n;
    e = e < -126 ? -126 : (e > 126 ? 126 : e);
    return p * __int_as_float((e + 127) << 23);
}

// bit-identical in sample and scan slow path (survivor guarantee needs it)
__device__ __forceinline__ float s_of(float a, float b, float c, float d, float m) {
    return fexp(a - m) + fexp(b - m) + fexp(c - m) + fexp(d - m);   // [1,4)
}
__device__ __forceinline__ int argmax4(float a, float b, float c, float d, float& m) {
    m = a; int am = 0;
    if (b > m) { m = b; am = 1; }
    if (c > m) { m = c; am = 2; }
    if (d > m) { m = d; am = 3; }
    return am;
}

// ---------------- kernel 1: 1/64 sampling (exact fexp s) -----------------
// grid (SVOX/8192 = 256, B), 128 threads: first 128 voxels of each 8192-run
__global__ void sample_kernel(const float* __restrict__ logits) {
    int b = blockIdx.y;
    unsigned v = blockIdx.x * 8192u + threadIdx.x;
    const float* base = logits + (size_t)b * CLS * SVOX;
    float a  = base[v];
    float x1 = base[SVOX + v];
    float x2 = base[2u * SVOX + v];
    float x3 = base[3u * SVOX + v];
    float m; int am = argmax4(a, x1, x2, x3, m);
    float s = s_of(a, x1, x2, x3, m);
    if (s < 2.0f) {                            // prob_argmax = 1/s > 0.5
        int g = b * CLS + am;
        unsigned p = atomicAdd(&g_scnt[g], 1u);
        if (p < SCAP) g_samp[g][p] = s;
    }
}

// ---------------- kernel 2: histogram cutoff (bin edge at sample rank 40)
// grid = B*CLS blocks, 256 threads. Also zeroes g_cnt for the scan.
__global__ __launch_bounds__(256) void cutoff_kernel() {
    __shared__ unsigned hist[256];
    __shared__ unsigned sT;
    const int g = blockIdx.x, tid = threadIdx.x;
    hist[tid] = 0u;
    __syncthreads();

    unsigned mc = g_scnt[g]; if (mc > SCAP) mc = SCAP;
    float cut;
    if (mc < (unsigned)RANK) {
        cut = 2.0f;                            // keep all candidates
    } else {
        for (unsigned i = tid; i < mc; i += 256) {
            unsigned d = __float_as_uint(g_samp[g][i]) - 0x3F800000u;  // [0,2^23)
            atomicAdd(&hist[d >> 15], 1u);
        }
        __syncthreads();
        if (tid == 0) {
            unsigned cum = 0; unsigned T = 255;
            for (int i = 0; i < 256; i++) {
                cum += hist[i];
                if (cum >= (unsigned)RANK) { T = (unsigned)i; break; }
            }
            sT = T;
        }
        __syncthreads();
        cut = __uint_as_float(0x3F800000u + ((sT + 1u) << 15));  // upper bin edge
    }
    if (tid == 0) {
        g_cut[g] = cut;
        g_td[g]  = -logf(cut - 1.0f) - 0.01f;  // gap >= td necessary for s < cut
        g_cnt[g] = 0u;                         // ready for scan
    }
}

// ---------------- kernel 3: exp-free full scan (HBM-bound) ----------------
// grid = B*(SVOX/2048) = 2048 blocks, 256 threads, 8 voxels/thread
__global__ __launch_bounds__(256) void scan_kernel(const float* __restrict__ logits) {
    const int tid = threadIdx.x;
    const int b   = blockIdx.x >> 10;
    const unsigned v0 = (unsigned)(blockIdx.x & 1023) * 2048u + (unsigned)tid * 8u;

    const float td = fminf(fminf(g_td[b * CLS],     g_td[b * CLS + 1]),
                           fminf(g_td[b * CLS + 2], g_td[b * CLS + 3]));

    const float4* p4 = (const float4*)(logits + (size_t)b * CLS * SVOX);
    float c0[8], c1[8], c2[8], c3[8];
    {
        float4 u, w;
        u = p4[(0u * SVOX + v0) >> 2]; w = p4[((0u * SVOX + v0) >> 2) + 1];
        c0[0]=u.x; c0[1]=u.y; c0[2]=u.z; c0[3]=u.w; c0[4]=w.x; c0[5]=w.y; c0[6]=w.z; c0[7]=w.w;
        u = p4[(1u * SVOX + v0) >> 2]; w = p4[((1u * SVOX + v0) >> 2) + 1];
        c1[0]=u.x; c1[1]=u.y; c1[2]=u.z; c1[3]=u.w; c1[4]=w.x; c1[5]=w.y; c1[6]=w.z; c1[7]=w.w;
        u = p4[(2u * SVOX + v0) >> 2]; w = p4[((2u * SVOX + v0) >> 2) + 1];
        c2[0]=u.x; c2[1]=u.y; c2[2]=u.z; c2[3]=u.w; c2[4]=w.x; c2[5]=w.y; c2[6]=w.z; c2[7]=w.w;
        u = p4[(3u * SVOX + v0) >> 2]; w = p4[((3u * SVOX + v0) >> 2) + 1];
        c3[0]=u.x; c3[1]=u.y; c3[2]=u.z; c3[3]=u.w; c3[4]=w.x; c3[5]=w.y; c3[6]=w.z; c3[7]=w.w;
    }

    unsigned mask = 0u;
#pragma unroll
    for (int i = 0; i < 8; i++) {
        float a = c0[i], bb = c1[i], cc = c2[i], dd = c3[i];
        float s1 = fmaxf(a, bb),  s2 = fminf(a, bb);
        float t1 = fmaxf(cc, dd), t2 = fminf(cc, dd);
        float hi  = fmaxf(s1, t1);
        float sec = fmaxf(fminf(s1, t1), fmaxf(s2, t2));
        if (hi - sec >= td) mask |= 1u << i;
    }

    if (__any_sync(FULLMASK, mask != 0u)) {    // warp-uniform rare branch
#pragma unroll
        for (int i = 0; i < 8; i++) {
            if (mask & (1u << i)) {
                float a = c0[i], bb = c1[i], cc = c2[i], dd = c3[i];
                float m; int am = argmax4(a, bb, cc, dd, m);
                float s = s_of(a, bb, cc, dd, m);
                int g = b * CLS + am;
                if (s < g_cut[g]) {            // cut<=2.0; ==2.0 => candidate test
                    u64 key = ((u64)__float_as_uint(s) << 21) | (u64)(v0 + (unsigned)i);
                    unsigned pos = atomicAdd(&g_cnt[g], 1u);
                    if (pos < (unsigned)CAP) g_surv[g][pos] = key;
                }
            }
        }
    }
}

// ---------------- double-precision exact key for final ranking -----------
__device__ __forceinline__ u64 dkey(u64 fkey, const float* __restrict__ base) {
    if (fkey == ~0ull) return ~0ull;
    unsigned idx = (unsigned)(fkey & 0x1FFFFFu);
    double a  = (double)base[idx];
    double x1 = (double)base[SVOX + idx];
    double x2 = (double)base[2u * SVOX + idx];
    double x3 = (double)base[3u * SVOX + idx];
    double m  = fmax(fmax(a, x1), fmax(x2, x3));
    double sd = exp(a - m) + exp(x1 - m) + exp(x2 - m) + exp(x3 - m);
    u64 diff = (u64)__double_as_longlong(sd) - 0x3FF0000000000000ull;
    if (diff > 0xFFFFFFFFFFFFFull) diff = 0xFFFFFFFFFFFFFull;
    return ((diff >> 9) << 21) | (u64)idx;     // asc = best; tie -> smaller idx
}

// ---------------- kernel 4: histogram top-48 + exact top-32 + output -----
// grid = B*CLS blocks, 256 threads
__global__ __launch_bounds__(256) void final_kernel(const float* __restrict__ logits,
                                                    float* __restrict__ out,
                                                    int out_size) {
    __shared__ unsigned hist[256];
    __shared__ u64 coll[COLCAP];               // 16 KB
    __shared__ unsigned s_nc;
    __shared__ int sF;
    __shared__ u64 s_top[TOPK];
    __shared__ u64 red[8];
    __shared__ u64 bc;

    const int g = blockIdx.x, tid = threadIdx.x;
    const int b = g >> 2, c = g & 3;
    const int w = (c + 3) & 3;                 // position in visit order [1,2,3,0]
    float* crd = out;                           // coords [B][128][3]
    const bool has_lab = out_size >= B * N_OUT * 4;
    float* lab = out + (out_size - B * N_OUT); // labels [B][128] at tail

    int cnt = (int)g_cnt[g];
    int m = cnt > CAP ? CAP : cnt;
    int k = cnt < NPTS ? cnt : NPTS; if (k > m) k = m;
    int off = 0;
    for (int o = 0; o < w; o++) {
        int t = (int)g_cnt[b * CLS + ((o + 1) & 3)];
        off += t < NPTS ? t : NPTS;
    }
    if (w == 3) {                              // last class fills padding tail
        int tot = off + k;
        for (int i = tot + tid; i < N_OUT; i += 256) {
            if (has_lab) lab[b * N_OUT + i] = -1.0f;
            crd[(b * N_OUT + i) * 3 + 0] = 0.0f;
            crd[(b * N_OUT + i) * 3 + 1] = 0.0f;
            crd[(b * N_OUT + i) * 3 + 2] = 0.0f;
        }
    }

    // bin geometry from this class's cut
    unsigned edge = __float_as_uint(g_cut[g]) - 0x3F800000u;       // <= 2^23
    int shift = 0;
    while ((edge >> shift) > 256u) shift++;

    hist[tid] = 0u;
    if (tid == 0) s_nc = 0u;
    __syncthreads();

    for (int i = tid; i < m; i += 256) {
        unsigned d = (unsigned)((g_surv[g][i] >> 21) - 0x3F800000u);
        atomicAdd(&hist[d >> shift], 1u);
    }
    __syncthreads();
    if (tid == 0) {
        unsigned target = (unsigned)(m < TOPK ? m : TOPK);
        unsigned cum = 0; int F = 255;
        for (int i = 0; i < 256; i++) {
            cum += hist[i];
            if (cum >= target) { F = i; break; }
        }
        sF = F;
    }
    __syncthreads();
    const int F = sF;
    for (int i = tid; i < m; i += 256) {
        u64 key = g_surv[g][i];
        unsigned d = (unsigned)((key >> 21) - 0x3F800000u);
        if ((int)(d >> shift) <= F) {
            unsigned pos = atomicAdd(&s_nc, 1u);
            if (pos < (unsigned)COLCAP) coll[pos] = key;
        }
    }
    __syncthreads();
    const unsigned nc = s_nc;

    if (nc <= (unsigned)COLCAP) {
        // warp-0 barrier-free extraction of TOPK smallest from coll[nc]
        if (tid < 32) {
            int lane = tid;
            if (lane < TOPK) s_top[lane] = ~0ull;
            if (lane < TOPK - 32) s_top[32 + lane] = ~0ull;
            __syncwarp();
            int n = (int)nc;
            u64 prev = 0;
            for (int r = 0; r < TOPK; r++) {
                u64 loc = ~0ull;
                for (int i = lane; i < n; i += 32) {
                    u64 kk = coll[i];
                    if (kk > prev && kk < loc) loc = kk;
                }
                for (int o = 16; o; o >>= 1) {
                    u64 t = __shfl_xor_sync(FULLMASK, loc, o);
                    if (t < loc) loc = t;
                }
                if (loc == ~0ull) break;
                if (lane == 0) s_top[r] = loc;
                prev = loc;
            }
            __syncwarp();
        }
    } else {
        // pathological fallback: block-wide extraction straight from global
        u64 prev = 0; int found = 0;
        for (int r = 0; r < TOPK; r++) {
            u64 loc = ~0ull;
            for (int i = tid; i < m; i += 256) {
                u64 kk = g_surv[g][i];
                if (kk > prev && kk < loc) loc = kk;
            }
            for (int o = 16; o; o >>= 1) {
                u64 t = __shfl_xor_sync(FULLMASK, loc, o);
                if (t < loc) loc = t;
            }
            if ((tid & 31) == 0) red[tid >> 5] = loc;
            __syncthreads();
            if (tid == 0) {
                u64 mn = red[0];
                for (int j = 1; j < 8; j++) if (red[j] < mn) mn = red[j];
                bc = mn; s_top[r] = mn;
            }
            __syncthreads();
            prev = bc;
            __syncthreads();
            if (prev == ~0ull) break;
            found = r + 1;
        }
        if (tid == 0)
            for (int r = found; r < TOPK; r++) s_top[r] = ~0ull;
    }
    __syncthreads();

    if (tid < 32) {                            // warp 0: exact re-rank of top-48
        const float* base = logits + (size_t)b * CLS * SVOX;
        u64 k0 = dkey(s_top[tid], base);
        u64 k1 = (tid < 16) ? dkey(s_top[32 + tid], base) : ~0ull;
        for (int r = 0; r < k; r++) {
            u64 mn = k0 < k1 ? k0 : k1;
            for (int o = 16; o; o >>= 1) {
                u64 t = __shfl_xor_sync(FULLMASK, mn, o);
                if (t < mn) mn = t;
            }
            if (mn == ~0ull) break;
            if (k0 == mn) k0 = ~0ull; else if (k1 == mn) k1 = ~0ull;
            if (tid == 0) {
                int idx  = (int)(mn & 0x1FFFFFull);
                int slot = off + r;
                if (has_lab) lab[b * N_OUT + slot] = (float)c;
                crd[(b * N_OUT + slot) * 3 + 0] = (float)(idx >> 14);
                crd[(b * N_OUT + slot) * 3 + 1] = (float)((idx >> 7) & 127);
                crd[(b * N_OUT + slot) * 3 + 2] = (float)(idx & 127);
            }
        }
    }

    // reset sample counter for the next replay (g_cnt is reset by cutoff)
    if (tid == 0) g_scnt[g] = 0u;
}

// ---------------- launch (kernel launches ONLY) ---------------------------
extern "C" void kernel_launch(void* const* d_in, const int* in_sizes, int n_in,
                              void* d_out, int out_size) {
    const long long want = (long long)B * CLS * SVOX;   // 16,777,216
    int li = 0;
    for (int i = 0; i < n_in; i++)
        if ((long long)in_sizes[i] == want) { li = i; break; }
    if ((long long)in_sizes[li] != want)
        for (int i = 1; i < n_in; i++)
            if (in_sizes[i] > in_sizes[li]) li = i;

    const float* logits = (const float*)d_in[li];
    float* out = (float*)d_out;

    sample_kernel<<<dim3(SVOX / 8192, B), 128>>>(logits);
    cutoff_kernel<<<B * CLS, 256>>>();
    scan_kernel<<<B * (SVOX / 2048), 256>>>(logits);
    final_kernel<<<B * CLS, 256>>>(logits, out, out_size);
}

// round 13
// speedup vs baseline: 14.2326x; 1.3614x over previous
#include <cuda_runtime.h>
#include <stdint.h>

typedef unsigned long long u64;
#define FULLMASK 0xffffffffu

static constexpr int B      = 2;
static constexpr int CLS    = 4;
static constexpr int NPTS   = 32;
static constexpr int N_OUT  = CLS * NPTS;     // 128
static constexpr int SVOX   = 1 << 21;        // 128^3
static constexpr int SCAP   = 8192;           // sample buffer per (b,c)
static constexpr int CAP    = 16384;          // survivor buffer per (b,c)
static constexpr int RANK   = 40;             // sample order stat (>= NPTS)
static constexpr int TOPK   = 48;             // f32 safety margin width
static constexpr int COLCAP = 256;            // refined collect capacity

// ---------------- static device scratch (no allocations) -----------------
__device__ float    g_samp[B * CLS][SCAP];
__device__ unsigned g_scnt[B * CLS];
__device__ float    g_cut[B * CLS];
__device__ float    g_td[B * CLS];
__device__ u64      g_surv[B * CLS][CAP];
__device__ unsigned g_cnt[B * CLS];

// ---------------- FMA-only exp (x <= 0), rel err ~1e-7, no MUFU ----------
__device__ __forceinline__ float fexp(float x) {
    float t = x * 1.4426950408889634f;
    float n = rintf(t);
    float r = fmaf(n, -0.69314718246459960938f, x);
    r       = fmaf(n,  1.90821492233381634e-9f, r);
    float p = 1.3888889e-3f;
    p = fmaf(p, r, 8.3333333e-3f);
    p = fmaf(p, r, 4.1666667e-2f);
    p = fmaf(p, r, 1.6666667e-1f);
    p = fmaf(p, r, 0.5f);
    p = fmaf(p, r, 1.0f);
    p = fmaf(p, r, 1.0f);                      // fexp(0) == 1 exactly
    int e = (int)n;
    e = e < -126 ? -126 : (e > 126 ? 126 : e);
    return p * __int_as_float((e + 127) << 23);
}

// bit-identical in sample and scan slow path (survivor guarantee needs it)
__device__ __forceinline__ float s_of(float a, float b, float c, float d, float m) {
    return fexp(a - m) + fexp(b - m) + fexp(c - m) + fexp(d - m);   // [1,4)
}
__device__ __forceinline__ int argmax4(float a, float b, float c, float d, float& m) {
    m = a; int am = 0;
    if (b > m) { m = b; am = 1; }
    if (c > m) { m = c; am = 2; }
    if (d > m) { m = d; am = 3; }
    return am;
}

// ---------------- kernel 1: 1/64 sampling (exact fexp s) -----------------
// grid (SVOX/8192 = 256, B), 128 threads: first 128 voxels of each 8192-run
__global__ void sample_kernel(const float* __restrict__ logits) {
    int b = blockIdx.y;
    unsigned v = blockIdx.x * 8192u + threadIdx.x;
    const float* base = logits + (size_t)b * CLS * SVOX;
    float a  = base[v];
    float x1 = base[SVOX + v];
    float x2 = base[2u * SVOX + v];
    float x3 = base[3u * SVOX + v];
    float m; int am = argmax4(a, x1, x2, x3, m);
    float s = s_of(a, x1, x2, x3, m);
    if (s < 2.0f) {                            // prob_argmax = 1/s > 0.5
        int g = b * CLS + am;
        unsigned p = atomicAdd(&g_scnt[g], 1u);
        if (p < SCAP) g_samp[g][p] = s;
    }
}

// ---------------- kernel 2: histogram cutoff (bin edge at sample rank 40)
// grid = B*CLS blocks, 256 threads. Also zeroes g_cnt for the scan.
__global__ __launch_bounds__(256) void cutoff_kernel() {
    __shared__ unsigned hist[256];
    __shared__ unsigned sT;
    const int g = blockIdx.x, tid = threadIdx.x;
    hist[tid] = 0u;
    __syncthreads();

    unsigned mc = g_scnt[g]; if (mc > SCAP) mc = SCAP;
    float cut;
    if (mc < (unsigned)RANK) {
        cut = 2.0f;                            // keep all candidates
    } else {
        for (unsigned i = tid; i < mc; i += 256) {
            unsigned d = __float_as_uint(g_samp[g][i]) - 0x3F800000u;  // [0,2^23)
            atomicAdd(&hist[d >> 15], 1u);
        }
        __syncthreads();
        if (tid == 0) {
            unsigned cum = 0; unsigned T = 255;
            for (int i = 0; i < 256; i++) {
                cum += hist[i];
                if (cum >= (unsigned)RANK) { T = (unsigned)i; break; }
            }
            sT = T;
        }
        __syncthreads();
        cut = __uint_as_float(0x3F800000u + ((sT + 1u) << 15));  // upper bin edge
    }
    if (tid == 0) {
        g_cut[g] = cut;
        g_td[g]  = -logf(cut - 1.0f) - 0.01f;  // gap >= td necessary for s < cut
        g_cnt[g] = 0u;                         // ready for scan
    }
}

// ---------------- kernel 3: exp-free full scan (HBM-bound) ----------------
// grid = B*(SVOX/2048) = 2048 blocks, 256 threads, 8 voxels/thread
__global__ __launch_bounds__(256) void scan_kernel(const float* __restrict__ logits) {
    const int tid = threadIdx.x;
    const int b   = blockIdx.x >> 10;
    const unsigned v0 = (unsigned)(blockIdx.x & 1023) * 2048u + (unsigned)tid * 8u;

    const float td = fminf(fminf(g_td[b * CLS],     g_td[b * CLS + 1]),
                           fminf(g_td[b * CLS + 2], g_td[b * CLS + 3]));

    const float4* p4 = (const float4*)(logits + (size_t)b * CLS * SVOX);
    float c0[8], c1[8], c2[8], c3[8];
    {
        float4 u, w;
        u = p4[(0u * SVOX + v0) >> 2]; w = p4[((0u * SVOX + v0) >> 2) + 1];
        c0[0]=u.x; c0[1]=u.y; c0[2]=u.z; c0[3]=u.w; c0[4]=w.x; c0[5]=w.y; c0[6]=w.z; c0[7]=w.w;
        u = p4[(1u * SVOX + v0) >> 2]; w = p4[((1u * SVOX + v0) >> 2) + 1];
        c1[0]=u.x; c1[1]=u.y; c1[2]=u.z; c1[3]=u.w; c1[4]=w.x; c1[5]=w.y; c1[6]=w.z; c1[7]=w.w;
        u = p4[(2u * SVOX + v0) >> 2]; w = p4[((2u * SVOX + v0) >> 2) + 1];
        c2[0]=u.x; c2[1]=u.y; c2[2]=u.z; c2[3]=u.w; c2[4]=w.x; c2[5]=w.y; c2[6]=w.z; c2[7]=w.w;
        u = p4[(3u * SVOX + v0) >> 2]; w = p4[((3u * SVOX + v0) >> 2) + 1];
        c3[0]=u.x; c3[1]=u.y; c3[2]=u.z; c3[3]=u.w; c3[4]=w.x; c3[5]=w.y; c3[6]=w.z; c3[7]=w.w;
    }

    unsigned mask = 0u;
#pragma unroll
    for (int i = 0; i < 8; i++) {
        float a = c0[i], bb = c1[i], cc = c2[i], dd = c3[i];
        float s1 = fmaxf(a, bb),  s2 = fminf(a, bb);
        float t1 = fmaxf(cc, dd), t2 = fminf(cc, dd);
        float hi  = fmaxf(s1, t1);
        float sec = fmaxf(fminf(s1, t1), fmaxf(s2, t2));
        if (hi - sec >= td) mask |= 1u << i;
    }

    if (__any_sync(FULLMASK, mask != 0u)) {    // warp-uniform rare branch
#pragma unroll
        for (int i = 0; i < 8; i++) {
            if (mask & (1u << i)) {
                float a = c0[i], bb = c1[i], cc = c2[i], dd = c3[i];
                float m; int am = argmax4(a, bb, cc, dd, m);
                float s = s_of(a, bb, cc, dd, m);
                int g = b * CLS + am;
                if (s < g_cut[g]) {
                    u64 key = ((u64)__float_as_uint(s) << 21) | (u64)(v0 + (unsigned)i);
                    unsigned pos = atomicAdd(&g_cnt[g], 1u);
                    if (pos < (unsigned)CAP) g_surv[g][pos] = key;
                }
            }
        }
    }
}

// ---------------- double-precision exact key for final ranking -----------
__device__ __forceinline__ u64 dkey(u64 fkey, const float* __restrict__ base) {
    if (fkey == ~0ull) return ~0ull;
    unsigned idx = (unsigned)(fkey & 0x1FFFFFu);
    double a  = (double)base[idx];
    double x1 = (double)base[SVOX + idx];
    double x2 = (double)base[2u * SVOX + idx];
    double x3 = (double)base[3u * SVOX + idx];
    double m  = fmax(fmax(a, x1), fmax(x2, x3));
    double sd = exp(a - m) + exp(x1 - m) + exp(x2 - m) + exp(x3 - m);
    u64 diff = (u64)__double_as_longlong(sd) - 0x3FF0000000000000ull;
    if (diff > 0xFFFFFFFFFFFFFull) diff = 0xFFFFFFFFFFFFFull;
    return ((diff >> 9) << 21) | (u64)idx;     // asc = best; tie -> smaller idx
}

// ---------------- kernel 4: 2-level refine + parallel exact sort + output
// grid = B*CLS blocks, 256 threads
__global__ __launch_bounds__(256) void final_kernel(const float* __restrict__ logits,
                                                    float* __restrict__ out,
                                                    int out_size) {
    __shared__ unsigned hist[256];
    __shared__ unsigned shist[256];
    __shared__ u64 coll[COLCAP];
    __shared__ u64 ek[COLCAP];
    __shared__ unsigned s_nc;
    __shared__ int sF, sF2;
    __shared__ unsigned sBelow;
    __shared__ u64 s_top[TOPK];
    __shared__ u64 red[8];
    __shared__ u64 bc;

    const int g = blockIdx.x, tid = threadIdx.x;
    const int b = g >> 2, c = g & 3;
    const int w = (c + 3) & 3;                 // position in visit order [1,2,3,0]
    float* crd = out;                           // coords [B][128][3]
    const bool has_lab = out_size >= B * N_OUT * 4;
    float* lab = out + (out_size - B * N_OUT); // labels [B][128] at tail

    int cnt = (int)g_cnt[g];
    int m = cnt > CAP ? CAP : cnt;
    int k = cnt < NPTS ? cnt : NPTS; if (k > m) k = m;
    int off = 0;
    for (int o = 0; o < w; o++) {
        int t = (int)g_cnt[b * CLS + ((o + 1) & 3)];
        off += t < NPTS ? t : NPTS;
    }
    if (w == 3) {                              // last class fills padding tail
        int tot = off + k;
        for (int i = tot + tid; i < N_OUT; i += 256) {
            if (has_lab) lab[b * N_OUT + i] = -1.0f;
            crd[(b * N_OUT + i) * 3 + 0] = 0.0f;
            crd[(b * N_OUT + i) * 3 + 1] = 0.0f;
            crd[(b * N_OUT + i) * 3 + 2] = 0.0f;
        }
    }

    const unsigned target = (unsigned)(m < TOPK ? m : TOPK);

    // bin geometry from this class's cut
    unsigned edge = __float_as_uint(g_cut[g]) - 0x3F800000u;       // <= 2^23
    int shift = 0;
    while ((edge >> shift) > 256u) shift++;
    const int sshift = shift > 8 ? shift - 8 : 0;

    // ---- level-1 histogram ----
    hist[tid] = 0u; shist[tid] = 0u;
    if (tid == 0) s_nc = 0u;
    __syncthreads();
    for (int i = tid; i < m; i += 256) {
        unsigned d = (unsigned)((g_surv[g][i] >> 21) - 0x3F800000u);
        atomicAdd(&hist[d >> shift], 1u);
    }
    __syncthreads();
    if (tid == 0) {
        unsigned cum = 0; int F = 255; unsigned below = 0;
        for (int i = 0; i < 256; i++) {
            unsigned h = hist[i];
            if (cum + h >= target) { F = i; below = cum; break; }
            cum += h;
        }
        sF = F; sBelow = below;
    }
    __syncthreads();
    const int F = sF; const unsigned below = sBelow;

    // ---- level-2 histogram of boundary bin F ----
    for (int i = tid; i < m; i += 256) {
        unsigned d = (unsigned)((g_surv[g][i] >> 21) - 0x3F800000u);
        if ((int)(d >> shift) == F)
            atomicAdd(&shist[(d - ((unsigned)F << shift)) >> sshift], 1u);
    }
    __syncthreads();
    if (tid == 0) {
        unsigned cum = below; int F2 = 255;
        for (int i = 0; i < 256; i++) {
            cum += shist[i];
            if (cum >= target) { F2 = i; break; }
        }
        sF2 = F2;
    }
    __syncthreads();
    const int F2 = sF2;

    // ---- collect refined downward-closed set ----
    for (int i = tid; i < m; i += 256) {
        u64 key = g_surv[g][i];
        unsigned d = (unsigned)((key >> 21) - 0x3F800000u);
        int bin = (int)(d >> shift);
        bool take = bin < F ||
                    (bin == F && (int)((d - ((unsigned)F << shift)) >> sshift) <= F2);
        if (take) {
            unsigned pos = atomicAdd(&s_nc, 1u);
            if (pos < (unsigned)COLCAP) coll[pos] = key;
        }
    }
    __syncthreads();
    const unsigned nc = s_nc;

    const float* base = logits + (size_t)b * CLS * SVOX;

    if (nc <= (unsigned)COLCAP) {
        // ---- parallel exact keys (one double-exp chain per thread) ----
        ek[tid] = (tid < (int)nc) ? dkey(coll[tid], base) : ~0ull;
        __syncthreads();

        // ---- bitonic sort of 256 keys, ascending ----
#pragma unroll 1
        for (int kk = 2; kk <= COLCAP; kk <<= 1) {
#pragma unroll 1
            for (int j = kk >> 1; j > 0; j >>= 1) {
                __syncthreads();
                int p = tid ^ j;
                if (p > tid) {
                    u64 x = ek[tid], y = ek[p];
                    bool asc = (tid & kk) == 0;
                    if ((x > y) == asc) { ek[tid] = y; ek[p] = x; }
                }
            }
        }
        __syncthreads();

        // ---- fully parallel output ----
        if (tid < k) {
            u64 key = ek[tid];
            int idx  = (int)(key & 0x1FFFFFull);
            int slot = off + tid;
            if (has_lab) lab[b * N_OUT + slot] = (float)c;
            crd[(b * N_OUT + slot) * 3 + 0] = (float)(idx >> 14);
            crd[(b * N_OUT + slot) * 3 + 1] = (float)((idx >> 7) & 127);
            crd[(b * N_OUT + slot) * 3 + 2] = (float)(idx & 127);
        }
    } else {
        // ---- pathological fallback: block-wide f32 extraction + serial rank
        u64 prev = 0; int found = 0;
        for (int r = 0; r < TOPK; r++) {
            u64 loc = ~0ull;
            for (int i = tid; i < m; i += 256) {
                u64 kk = g_surv[g][i];
                if (kk > prev && kk < loc) loc = kk;
            }
            for (int o = 16; o; o >>= 1) {
                u64 t = __shfl_xor_sync(FULLMASK, loc, o);
                if (t < loc) loc = t;
            }
            if ((tid & 31) == 0) red[tid >> 5] = loc;
            __syncthreads();
            if (tid == 0) {
                u64 mn = red[0];
                for (int j = 1; j < 8; j++) if (red[j] < mn) mn = red[j];
                bc = mn; s_top[r] = mn;
            }
            __syncthreads();
            prev = bc;
            __syncthreads();
            if (prev == ~0ull) break;
            found = r + 1;
        }
        if (tid == 0)
            for (int r = found; r < TOPK; r++) s_top[r] = ~0ull;
        __syncthreads();

        if (tid < 32) {
            u64 k0 = dkey(s_top[tid], base);
            u64 k1 = (tid < 16) ? dkey(s_top[32 + tid], base) : ~0ull;
            for (int r = 0; r < k; r++) {
                u64 mn = k0 < k1 ? k0 : k1;
                for (int o = 16; o; o >>= 1) {
                    u64 t = __shfl_xor_sync(FULLMASK, mn, o);
                    if (t < mn) mn = t;
                }
                if (mn == ~0ull) break;
                if (k0 == mn) k0 = ~0ull; else if (k1 == mn) k1 = ~0ull;
                if (tid == 0) {
                    int idx  = (int)(mn & 0x1FFFFFull);
                    int slot = off + r;
                    if (has_lab) lab[b * N_OUT + slot] = (float)c;
                    crd[(b * N_OUT + slot) * 3 + 0] = (float)(idx >> 14);
                    crd[(b * N_OUT + slot) * 3 + 1] = (float)((idx >> 7) & 127);
                    crd[(b * N_OUT + slot) * 3 + 2] = (float)(idx & 127);
                }
            }
        }
    }

    // reset sample counter for the next replay (g_cnt is reset by cutoff)
    if (tid == 0) g_scnt[g] = 0u;
}

// ---------------- launch (kernel launches ONLY) ---------------------------
extern "C" void kernel_launch(void* const* d_in, const int* in_sizes, int n_in,
                              void* d_out, int out_size) {
    const long long want = (long long)B * CLS * SVOX;   // 16,777,216
    int li = 0;
    for (int i = 0; i < n_in; i++)
        if ((long long)in_sizes[i] == want) { li = i; break; }
    if ((long long)in_sizes[li] != want)
        for (int i = 1; i < n_in; i++)
            if (in_sizes[i] > in_sizes[li]) li = i;

    const float* logits = (const float*)d_in[li];
    float* out = (float*)d_out;

    sample_kernel<<<dim3(SVOX / 8192, B), 128>>>(logits);
    cutoff_kernel<<<B * CLS, 256>>>();
    scan_kernel<<<B * (SVOX / 2048), 256>>>(logits);
    final_kernel<<<B * CLS, 256>>>(logits, out, out_size);
}

// round 14
// speedup vs baseline: 16.4199x; 1.1537x over previous
#include <cuda_runtime.h>
#include <stdint.h>

typedef unsigned long long u64;
#define FULLMASK 0xffffffffu

static constexpr int B       = 2;
static constexpr int CLS     = 4;
static constexpr int NPTS    = 32;
static constexpr int N_OUT   = CLS * NPTS;    // 128
static constexpr int SVOX    = 1 << 21;       // 128^3
static constexpr int SCAP    = 8192;          // sample buffer per (b,c)
static constexpr int CAP     = 16384;         // survivor buffer per (b,c)
static constexpr int RANK    = 40;            // sample order stat (>= NPTS)
static constexpr int TOPK    = 48;            // f32 safety margin width
static constexpr int COLCAP  = 256;           // refined collect capacity
static constexpr int SHSTAGE = 4096;          // survivors staged in shared

// ---------------- static device scratch (no allocations) -----------------
__device__ float    g_samp[B * CLS][SCAP];
__device__ unsigned g_scnt[B * CLS];
__device__ float    g_cut[B * CLS];
__device__ float    g_td[B * CLS];
__device__ u64      g_surv[B * CLS][CAP];
__device__ unsigned g_cnt[B * CLS];

// ---------------- FMA-only exp (x <= 0), rel err ~1e-7, no MUFU ----------
__device__ __forceinline__ float fexp(float x) {
    float t = x * 1.4426950408889634f;
    float n = rintf(t);
    float r = fmaf(n, -0.69314718246459960938f, x);
    r       = fmaf(n,  1.90821492233381634e-9f, r);
    float p = 1.3888889e-3f;
    p = fmaf(p, r, 8.3333333e-3f);
    p = fmaf(p, r, 4.1666667e-2f);
    p = fmaf(p, r, 1.6666667e-1f);
    p = fmaf(p, r, 0.5f);
    p = fmaf(p, r, 1.0f);
    p = fmaf(p, r, 1.0f);                      // fexp(0) == 1 exactly
    int e = (int)n;
    e = e < -126 ? -126 : (e > 126 ? 126 : e);
    return p * __int_as_float((e + 127) << 23);
}

// bit-identical in sample and scan slow path (survivor guarantee needs it)
__device__ __forceinline__ float s_of(float a, float b, float c, float d, float m) {
    return fexp(a - m) + fexp(b - m) + fexp(c - m) + fexp(d - m);   // [1,4)
}
__device__ __forceinline__ int argmax4(float a, float b, float c, float d, float& m) {
    m = a; int am = 0;
    if (b > m) { m = b; am = 1; }
    if (c > m) { m = c; am = 2; }
    if (d > m) { m = d; am = 3; }
    return am;
}

// ---------------- kernel 1: 1/64 sampling (exact fexp s) -----------------
__global__ void sample_kernel(const float* __restrict__ logits) {
    int b = blockIdx.y;
    unsigned v = blockIdx.x * 8192u + threadIdx.x;
    const float* base = logits + (size_t)b * CLS * SVOX;
    float a  = base[v];
    float x1 = base[SVOX + v];
    float x2 = base[2u * SVOX + v];
    float x3 = base[3u * SVOX + v];
    float m; int am = argmax4(a, x1, x2, x3, m);
    float s = s_of(a, x1, x2, x3, m);
    if (s < 2.0f) {                            // prob_argmax = 1/s > 0.5
        int g = b * CLS + am;
        unsigned p = atomicAdd(&g_scnt[g], 1u);
        if (p < SCAP) g_samp[g][p] = s;
    }
}

// ---------------- kernel 2: histogram cutoff (bin edge at sample rank 40)
__global__ __launch_bounds__(256) void cutoff_kernel() {
    __shared__ unsigned hist[256];
    __shared__ unsigned sT;
    const int g = blockIdx.x, tid = threadIdx.x;
    hist[tid] = 0u;
    __syncthreads();

    unsigned mc = g_scnt[g]; if (mc > SCAP) mc = SCAP;
    float cut;
    if (mc < (unsigned)RANK) {
        cut = 2.0f;                            // keep all candidates
    } else {
        for (unsigned i = tid; i < mc; i += 256) {
            unsigned d = __float_as_uint(g_samp[g][i]) - 0x3F800000u;  // [0,2^23)
            atomicAdd(&hist[d >> 15], 1u);
        }
        __syncthreads();
        if (tid == 0) {
            unsigned cum = 0; unsigned T = 255;
            for (int i = 0; i < 256; i++) {
                cum += hist[i];
                if (cum >= (unsigned)RANK) { T = (unsigned)i; break; }
            }
            sT = T;
        }
        __syncthreads();
        cut = __uint_as_float(0x3F800000u + ((sT + 1u) << 15));  // upper bin edge
    }
    if (tid == 0) {
        g_cut[g] = cut;
        g_td[g]  = -logf(cut - 1.0f) - 0.01f;  // gap >= td necessary for s < cut
        g_cnt[g] = 0u;                         // ready for scan
    }
}

// ---------------- kernel 3: exp-free full scan (HBM-bound) ----------------
// grid = B*(SVOX/2048) = 2048 blocks, 256 threads, 8 voxels/thread
__global__ __launch_bounds__(256) void scan_kernel(const float* __restrict__ logits) {
    const int tid = threadIdx.x;
    const int b   = blockIdx.x >> 10;
    const unsigned v0 = (unsigned)(blockIdx.x & 1023) * 2048u + (unsigned)tid * 8u;

    const float td = fminf(fminf(g_td[b * CLS],     g_td[b * CLS + 1]),
                           fminf(g_td[b * CLS + 2], g_td[b * CLS + 3]));

    const float4* p4 = (const float4*)(logits + (size_t)b * CLS * SVOX);
    float c0[8], c1[8], c2[8], c3[8];
    {
        float4 u, w;
        u = p4[(0u * SVOX + v0) >> 2]; w = p4[((0u * SVOX + v0) >> 2) + 1];
        c0[0]=u.x; c0[1]=u.y; c0[2]=u.z; c0[3]=u.w; c0[4]=w.x; c0[5]=w.y; c0[6]=w.z; c0[7]=w.w;
        u = p4[(1u * SVOX + v0) >> 2]; w = p4[((1u * SVOX + v0) >> 2) + 1];
        c1[0]=u.x; c1[1]=u.y; c1[2]=u.z; c1[3]=u.w; c1[4]=w.x; c1[5]=w.y; c1[6]=w.z; c1[7]=w.w;
        u = p4[(2u * SVOX + v0) >> 2]; w = p4[((2u * SVOX + v0) >> 2) + 1];
        c2[0]=u.x; c2[1]=u.y; c2[2]=u.z; c2[3]=u.w; c2[4]=w.x; c2[5]=w.y; c2[6]=w.z; c2[7]=w.w;
        u = p4[(3u * SVOX + v0) >> 2]; w = p4[((3u * SVOX + v0) >> 2) + 1];
        c3[0]=u.x; c3[1]=u.y; c3[2]=u.z; c3[3]=u.w; c3[4]=w.x; c3[5]=w.y; c3[6]=w.z; c3[7]=w.w;
    }

    unsigned mask = 0u;
#pragma unroll
    for (int i = 0; i < 8; i++) {
        float a = c0[i], bb = c1[i], cc = c2[i], dd = c3[i];
        float s1 = fmaxf(a, bb),  s2 = fminf(a, bb);
        float t1 = fmaxf(cc, dd), t2 = fminf(cc, dd);
        float hi  = fmaxf(s1, t1);
        float sec = fmaxf(fminf(s1, t1), fmaxf(s2, t2));
        if (hi - sec >= td) mask |= 1u << i;
    }

    if (__any_sync(FULLMASK, mask != 0u)) {    // warp-uniform rare branch
#pragma unroll
        for (int i = 0; i < 8; i++) {
            if (mask & (1u << i)) {
                float a = c0[i], bb = c1[i], cc = c2[i], dd = c3[i];
                float m; int am = argmax4(a, bb, cc, dd, m);
                float s = s_of(a, bb, cc, dd, m);
                int g = b * CLS + am;
                if (s < g_cut[g]) {
                    u64 key = ((u64)__float_as_uint(s) << 21) | (u64)(v0 + (unsigned)i);
                    unsigned pos = atomicAdd(&g_cnt[g], 1u);
                    if (pos < (unsigned)CAP) g_surv[g][pos] = key;
                }
            }
        }
    }
}

// ---------------- double-precision exact key for final ranking -----------
__device__ __forceinline__ u64 dkey(u64 fkey, const float* __restrict__ base) {
    if (fkey == ~0ull) return ~0ull;
    unsigned idx = (unsigned)(fkey & 0x1FFFFFu);
    double a  = (double)base[idx];
    double x1 = (double)base[SVOX + idx];
    double x2 = (double)base[2u * SVOX + idx];
    double x3 = (double)base[3u * SVOX + idx];
    double m  = fmax(fmax(a, x1), fmax(x2, x3));
    double sd = exp(a - m) + exp(x1 - m) + exp(x2 - m) + exp(x3 - m);
    u64 diff = (u64)__double_as_longlong(sd) - 0x3FF0000000000000ull;
    if (diff > 0xFFFFFFFFFFFFFull) diff = 0xFFFFFFFFFFFFFull;
    return ((diff >> 9) << 21) | (u64)idx;     // asc = best; tie -> smaller idx
}

// ---------------- kernel 4: stage + hist + rank-select + output -----------
// grid = B*CLS blocks, 256 threads; ~4 barriers on the common path
__global__ __launch_bounds__(256) void final_kernel(const float* __restrict__ logits,
                                                    float* __restrict__ out,
                                                    int out_size) {
    __shared__ u64 sk[SHSTAGE];                // 32 KB survivor stage
    __shared__ unsigned hist[256];
    __shared__ unsigned shist[256];
    __shared__ u64 coll[COLCAP];
    __shared__ u64 ek[COLCAP];
    __shared__ unsigned s_nc;
    __shared__ int sF, sF2;
    __shared__ unsigned sBelow;
    __shared__ u64 s_top[TOPK];
    __shared__ u64 red[8];
    __shared__ u64 bc;

    const int g = blockIdx.x, tid = threadIdx.x;
    const int b = g >> 2, c = g & 3;
    const int w = (c + 3) & 3;                 // position in visit order [1,2,3,0]
    float* crd = out;                           // coords [B][128][3]
    const bool has_lab = out_size >= B * N_OUT * 4;
    float* lab = out + (out_size - B * N_OUT); // labels [B][128] at tail

    int cnt = (int)g_cnt[g];
    int m = cnt > CAP ? CAP : cnt;
    int k = cnt < NPTS ? cnt : NPTS; if (k > m) k = m;
    int off = 0;
    for (int o = 0; o < w; o++) {
        int t = (int)g_cnt[b * CLS + ((o + 1) & 3)];
        off += t < NPTS ? t : NPTS;
    }
    if (w == 3) {                              // last class fills padding tail
        int tot = off + k;
        for (int i = tot + tid; i < N_OUT; i += 256) {
            if (has_lab) lab[b * N_OUT + i] = -1.0f;
            crd[(b * N_OUT + i) * 3 + 0] = 0.0f;
            crd[(b * N_OUT + i) * 3 + 1] = 0.0f;
            crd[(b * N_OUT + i) * 3 + 2] = 0.0f;
        }
    }

    const unsigned target = (unsigned)(m < TOPK ? m : TOPK);

    // bin geometry from this class's cut
    unsigned edge = __float_as_uint(g_cut[g]) - 0x3F800000u;       // <= 2^23
    int shift = 0;
    while ((edge >> shift) > 256u) shift++;
    const int sshift = shift > 8 ? shift - 8 : 0;

    // ---- single global sweep: stage to shared + level-1 histogram ----
    hist[tid] = 0u;
    if (tid == 0) s_nc = 0u;
    __syncthreads();
    for (int i = tid; i < m; i += 256) {
        u64 key = g_surv[g][i];
        if (i < SHSTAGE) sk[i] = key;
        unsigned d = (unsigned)((key >> 21) - 0x3F800000u);
        atomicAdd(&hist[d >> shift], 1u);
    }
    __syncthreads();
    if (tid == 0) {
        unsigned cum = 0; int F = 255; unsigned below = 0;
        for (int i = 0; i < 256; i++) {
            unsigned h = hist[i];
            if (cum + h >= target) { F = i; below = cum; break; }
            cum += h;
        }
        sF = F; sBelow = below;
    }
    __syncthreads();
    const int F = sF;
    const unsigned nc1 = sBelow + hist[F];

    if (nc1 <= (unsigned)COLCAP) {
        // ---- common path: collect bin <= F from shared ----
        for (int i = tid; i < m; i += 256) {
            u64 key = (i < SHSTAGE) ? sk[i] : g_surv[g][i];
            unsigned d = (unsigned)((key >> 21) - 0x3F800000u);
            if ((int)(d >> shift) <= F)
                coll[atomicAdd(&s_nc, 1u)] = key;
        }
    } else {
        // ---- rare: level-2 refine of boundary bin ----
        shist[tid] = 0u;
        __syncthreads();
        for (int i = tid; i < m; i += 256) {
            u64 key = (i < SHSTAGE) ? sk[i] : g_surv[g][i];
            unsigned d = (unsigned)((key >> 21) - 0x3F800000u);
            if ((int)(d >> shift) == F)
                atomicAdd(&shist[(d - ((unsigned)F << shift)) >> sshift], 1u);
        }
        __syncthreads();
        if (tid == 0) {
            unsigned cum = sBelow; int F2 = 255;
            for (int i = 0; i < 256; i++) {
                cum += shist[i];
                if (cum >= target) { F2 = i; break; }
            }
            sF2 = F2;
        }
        __syncthreads();
        const int F2 = sF2;
        for (int i = tid; i < m; i += 256) {
            u64 key = (i < SHSTAGE) ? sk[i] : g_surv[g][i];
            unsigned d = (unsigned)((key >> 21) - 0x3F800000u);
            int bin = (int)(d >> shift);
            bool take = bin < F ||
                        (bin == F && (int)((d - ((unsigned)F << shift)) >> sshift) <= F2);
            if (take) {
                unsigned pos = atomicAdd(&s_nc, 1u);
                if (pos < (unsigned)COLCAP) coll[pos] = key;
            }
        }
    }
    __syncthreads();
    const unsigned nc = s_nc;

    const float* base = logits + (size_t)b * CLS * SVOX;

    if (nc <= (unsigned)COLCAP) {
        // ---- parallel exact keys (one double-exp chain per thread) ----
        ek[tid] = (tid < (int)nc) ? dkey(coll[tid], base) : ~0ull;
        __syncthreads();

        // ---- O(n^2) rank selection (keys unique), fully parallel output --
        if (tid < (int)nc) {
            u64 mine = ek[tid];
            int rank = 0;
            for (int j = 0; j < (int)nc; j++) rank += (ek[j] < mine);
            if (rank < k) {
                int idx  = (int)(mine & 0x1FFFFFull);
                int slot = off + rank;
                if (has_lab) lab[b * N_OUT + slot] = (float)c;
                crd[(b * N_OUT + slot) * 3 + 0] = (float)(idx >> 14);
                crd[(b * N_OUT + slot) * 3 + 1] = (float)((idx >> 7) & 127);
                crd[(b * N_OUT + slot) * 3 + 2] = (float)(idx & 127);
            }
        }
    } else {
        // ---- ultimate fallback (massive f32-key ties): serial extraction --
        u64 prev = 0; int found = 0;
        for (int r = 0; r < TOPK; r++) {
            u64 loc = ~0ull;
            for (int i = tid; i < m; i += 256) {
                u64 kk = (i < SHSTAGE) ? sk[i] : g_surv[g][i];
                if (kk > prev && kk < loc) loc = kk;
            }
            for (int o = 16; o; o >>= 1) {
                u64 t = __shfl_xor_sync(FULLMASK, loc, o);
                if (t < loc) loc = t;
            }
            if ((tid & 31) == 0) red[tid >> 5] = loc;
            __syncthreads();
            if (tid == 0) {
                u64 mn = red[0];
                for (int j = 1; j < 8; j++) if (red[j] < mn) mn = red[j];
                bc = mn; s_top[r] = mn;
            }
            __syncthreads();
            prev = bc;
            __syncthreads();
            if (prev == ~0ull) break;
            found = r + 1;
        }
        if (tid == 0)
            for (int r = found; r < TOPK; r++) s_top[r] = ~0ull;
        __syncthreads();

        if (tid < 32) {
            u64 k0 = dkey(s_top[tid], base);
            u64 k1 = (tid < 16) ? dkey(s_top[32 + tid], base) : ~0ull;
            for (int r = 0; r < k; r++) {
                u64 mn = k0 < k1 ? k0 : k1;
                for (int o = 16; o; o >>= 1) {
                    u64 t = __shfl_xor_sync(FULLMASK, mn, o);
                    if (t < mn) mn = t;
                }
                if (mn == ~0ull) break;
                if (k0 == mn) k0 = ~0ull; else if (k1 == mn) k1 = ~0ull;
                if (tid == 0) {
                    int idx  = (int)(mn & 0x1FFFFFull);
                    int slot = off + r;
                    if (has_lab) lab[b * N_OUT + slot] = (float)c;
                    crd[(b * N_OUT + slot) * 3 + 0] = (float)(idx >> 14);
                    crd[(b * N_OUT + slot) * 3 + 1] = (float)((idx >> 7) & 127);
                    crd[(b * N_OUT + slot) * 3 + 2] = (float)(idx & 127);
                }
            }
        }
    }

    // reset sample counter for the next replay (g_cnt is reset by cutoff)
    if (tid == 0) g_scnt[g] = 0u;
}

// ---------------- launch (kernel launches ONLY) ---------------------------
extern "C" void kernel_launch(void* const* d_in, const int* in_sizes, int n_in,
                              void* d_out, int out_size) {
    const long long want = (long long)B * CLS * SVOX;   // 16,777,216
    int li = 0;
    for (int i = 0; i < n_in; i++)
        if ((long long)in_sizes[i] == want) { li = i; break; }
    if ((long long)in_sizes[li] != want)
        for (int i = 1; i < n_in; i++)
            if (in_sizes[i] > in_sizes[li]) li = i;

    const float* logits = (const float*)d_in[li];
    float* out = (float*)d_out;

    sample_kernel<<<dim3(SVOX / 8192, B), 128>>>(logits);
    cutoff_kernel<<<B * CLS, 256>>>();
    scan_kernel<<<B * (SVOX / 2048), 256>>>(logits);
    final_kernel<<<B * CLS, 256>>>(logits, out, out_size);
}

// round 15
// speedup vs baseline: 16.4319x; 1.0007x over previous
#include <cuda_runtime.h>
#include <stdint.h>

typedef unsigned long long u64;
#define FULLMASK 0xffffffffu

static constexpr int B       = 2;
static constexpr int CLS     = 4;
static constexpr int NPTS    = 32;
static constexpr int N_OUT   = CLS * NPTS;    // 128
static constexpr int SVOX    = 1 << 21;       // 128^3
static constexpr int SCAP    = 8192;          // sample buffer per (b,c)
static constexpr int CAP     = 16384;         // survivor buffer per (b,c)
static constexpr int RANK    = 40;            // sample order stat (>= NPTS)
static constexpr int TOPK    = 48;            // f32 safety margin width
static constexpr int COLCAP  = 256;           // refined collect capacity
static constexpr int SHSTAGE = 4096;          // survivors staged in shared

// ---------------- static device scratch (no allocations) -----------------
__device__ float    g_samp[B * CLS][SCAP];
__device__ unsigned g_scnt[B * CLS];
__device__ float    g_cut[B * CLS];
__device__ float    g_td[B * CLS];
__device__ u64      g_surv[B * CLS][CAP];
__device__ unsigned g_cnt[B * CLS];

// ---------------- FMA-only exp (x <= 0), rel err ~1e-7, no MUFU ----------
__device__ __forceinline__ float fexp(float x) {
    float t = x * 1.4426950408889634f;
    float n = rintf(t);
    float r = fmaf(n, -0.69314718246459960938f, x);
    r       = fmaf(n,  1.90821492233381634e-9f, r);
    float p = 1.3888889e-3f;
    p = fmaf(p, r, 8.3333333e-3f);
    p = fmaf(p, r, 4.1666667e-2f);
    p = fmaf(p, r, 1.6666667e-1f);
    p = fmaf(p, r, 0.5f);
    p = fmaf(p, r, 1.0f);
    p = fmaf(p, r, 1.0f);                      // fexp(0) == 1 exactly
    int e = (int)n;
    e = e < -126 ? -126 : (e > 126 ? 126 : e);
    return p * __int_as_float((e + 127) << 23);
}

// bit-identical in sample and scan slow path (survivor guarantee needs it)
__device__ __forceinline__ float s_of(float a, float b, float c, float d, float m) {
    return fexp(a - m) + fexp(b - m) + fexp(c - m) + fexp(d - m);   // [1,4)
}
__device__ __forceinline__ int argmax4(float a, float b, float c, float d, float& m) {
    m = a; int am = 0;
    if (b > m) { m = b; am = 1; }
    if (c > m) { m = c; am = 2; }
    if (d > m) { m = d; am = 3; }
    return am;
}

// ---- parallel 256-bin histogram crossing: finds first bin F with
// base + cum(hist[0..F]) >= target; writes F and below=cum(hist[0..F-1])+base.
// Caller must init *sF (=255) and *sBelow (=0) and barrier BEFORE the hist
// sweep; this helper starts with hist[] valid and ends with a barrier.
__device__ __forceinline__ void hist_cross(const unsigned* hist, unsigned basecum,
                                           unsigned target, unsigned* wsum,
                                           volatile unsigned* sF,
                                           volatile unsigned* sBelow, int tid) {
    unsigned h = hist[tid];
    unsigned lane = tid & 31, wd = (unsigned)tid >> 5;
    unsigned v = h;
    for (int d = 1; d < 32; d <<= 1) {
        unsigned t = __shfl_up_sync(FULLMASK, v, d);
        if (lane >= d) v += t;
    }
    if (lane == 31) wsum[wd] = v;
    __syncthreads();
    unsigned add = basecum;
    for (unsigned j = 0; j < wd; j++) add += wsum[j];
    unsigned incl = v + add;
    unsigned excl = incl - h;
    if (incl >= target && excl < target) {     // unique first-crossing thread
        *sF = (unsigned)tid;
        *sBelow = excl;
    }
    __syncthreads();
}

// ---------------- kernel 1: 1/64 sampling (exact fexp s) -----------------
__global__ void sample_kernel(const float* __restrict__ logits) {
    int b = blockIdx.y;
    unsigned v = blockIdx.x * 8192u + threadIdx.x;
    const float* base = logits + (size_t)b * CLS * SVOX;
    float a  = base[v];
    float x1 = base[SVOX + v];
    float x2 = base[2u * SVOX + v];
    float x3 = base[3u * SVOX + v];
    float m; int am = argmax4(a, x1, x2, x3, m);
    float s = s_of(a, x1, x2, x3, m);
    if (s < 2.0f) {                            // prob_argmax = 1/s > 0.5
        int g = b * CLS + am;
        unsigned p = atomicAdd(&g_scnt[g], 1u);
        if (p < SCAP) g_samp[g][p] = s;
    }
}

// ---------------- kernel 2: histogram cutoff (parallel crossing) ----------
__global__ __launch_bounds__(256) void cutoff_kernel() {
    __shared__ unsigned hist[256];
    __shared__ unsigned wsum[8];
    __shared__ unsigned sF, sBelow;
    const int g = blockIdx.x, tid = threadIdx.x;
    hist[tid] = 0u;
    if (tid == 0) { sF = 255u; sBelow = 0u; }
    __syncthreads();

    unsigned mc = g_scnt[g]; if (mc > SCAP) mc = SCAP;
    float cut;
    if (mc < (unsigned)RANK) {
        cut = 2.0f;                            // keep all candidates
        __syncthreads();                       // match helper's barrier count
        __syncthreads();
    } else {
        for (unsigned i = tid; i < mc; i += 256) {
            unsigned d = __float_as_uint(g_samp[g][i]) - 0x3F800000u;  // [0,2^23)
            atomicAdd(&hist[d >> 15], 1u);
        }
        __syncthreads();
        hist_cross(hist, 0u, (unsigned)RANK, wsum, &sF, &sBelow, tid);
        cut = __uint_as_float(0x3F800000u + ((sF + 1u) << 15));  // upper bin edge
    }
    if (tid == 0) {
        g_cut[g] = cut;
        g_td[g]  = -logf(cut - 1.0f) - 0.01f;  // gap > td necessary for s < cut
        g_cnt[g] = 0u;                         // ready for scan
    }
}

// ---------------- kernel 3: exp-free full scan (HBM-bound) ----------------
// grid = B*(SVOX/2048) = 2048 blocks, 256 threads, 8 voxels/thread
__global__ __launch_bounds__(256) void scan_kernel(const float* __restrict__ logits) {
    const int tid = threadIdx.x;
    const int b   = blockIdx.x >> 10;
    const unsigned v0 = (unsigned)(blockIdx.x & 1023) * 2048u + (unsigned)tid * 8u;

    const float td = fminf(fminf(g_td[b * CLS],     g_td[b * CLS + 1]),
                           fminf(g_td[b * CLS + 2], g_td[b * CLS + 3]));

    const float4* p4 = (const float4*)(logits + (size_t)b * CLS * SVOX);
    float c0[8], c1[8], c2[8], c3[8];
    {
        float4 u, w;
        u = p4[(0u * SVOX + v0) >> 2]; w = p4[((0u * SVOX + v0) >> 2) + 1];
        c0[0]=u.x; c0[1]=u.y; c0[2]=u.z; c0[3]=u.w; c0[4]=w.x; c0[5]=w.y; c0[6]=w.z; c0[7]=w.w;
        u = p4[(1u * SVOX + v0) >> 2]; w = p4[((1u * SVOX + v0) >> 2) + 1];
        c1[0]=u.x; c1[1]=u.y; c1[2]=u.z; c1[3]=u.w; c1[4]=w.x; c1[5]=w.y; c1[6]=w.z; c1[7]=w.w;
        u = p4[(2u * SVOX + v0) >> 2]; w = p4[((2u * SVOX + v0) >> 2) + 1];
        c2[0]=u.x; c2[1]=u.y; c2[2]=u.z; c2[3]=u.w; c2[4]=w.x; c2[5]=w.y; c2[6]=w.z; c2[7]=w.w;
        u = p4[(3u * SVOX + v0) >> 2]; w = p4[((3u * SVOX + v0) >> 2) + 1];
        c3[0]=u.x; c3[1]=u.y; c3[2]=u.z; c3[3]=u.w; c3[4]=w.x; c3[5]=w.y; c3[6]=w.z; c3[7]=w.w;
    }

    // cheap necessary screen: hi - sec <= |max(pair1) - max(pair2)|
    unsigned mask = 0u;
#pragma unroll
    for (int i = 0; i < 8; i++) {
        float m1 = fmaxf(c0[i], c1[i]);
        float m2 = fmaxf(c2[i], c3[i]);
        if (fabsf(m1 - m2) >= td) mask |= 1u << i;
    }

    if (__any_sync(FULLMASK, mask != 0u)) {    // warp-uniform rare branch
#pragma unroll
        for (int i = 0; i < 8; i++) {
            if (mask & (1u << i)) {
                float a = c0[i], bb = c1[i], cc = c2[i], dd = c3[i];
                float m; int am = argmax4(a, bb, cc, dd, m);
                float s = s_of(a, bb, cc, dd, m);
                int g = b * CLS + am;
                if (s < g_cut[g]) {
                    u64 key = ((u64)__float_as_uint(s) << 21) | (u64)(v0 + (unsigned)i);
                    unsigned pos = atomicAdd(&g_cnt[g], 1u);
                    if (pos < (unsigned)CAP) g_surv[g][pos] = key;
                }
            }
        }
    }
}

// ---------------- double-precision exact key for final ranking -----------
__device__ __forceinline__ u64 dkey(u64 fkey, const float* __restrict__ base) {
    if (fkey == ~0ull) return ~0ull;
    unsigned idx = (unsigned)(fkey & 0x1FFFFFu);
    double a  = (double)base[idx];
    double x1 = (double)base[SVOX + idx];
    double x2 = (double)base[2u * SVOX + idx];
    double x3 = (double)base[3u * SVOX + idx];
    double m  = fmax(fmax(a, x1), fmax(x2, x3));
    double sd = exp(a - m) + exp(x1 - m) + exp(x2 - m) + exp(x3 - m);
    u64 diff = (u64)__double_as_longlong(sd) - 0x3FF0000000000000ull;
    if (diff > 0xFFFFFFFFFFFFFull) diff = 0xFFFFFFFFFFFFFull;
    return ((diff >> 9) << 21) | (u64)idx;     // asc = best; tie -> smaller idx
}

// ---------------- kernel 4: stage + parallel hist + rank-select ----------
// grid = B*CLS blocks, 256 threads
__global__ __launch_bounds__(256) void final_kernel(const float* __restrict__ logits,
                                                    float* __restrict__ out,
                                                    int out_size) {
    __shared__ u64 sk[SHSTAGE];                // 32 KB survivor stage
    __shared__ unsigned hist[256];
    __shared__ unsigned shist[256];
    __shared__ unsigned wsum[8];
    __shared__ unsigned sF, sBelow, sF2, sB2;
    __shared__ u64 coll[COLCAP];
    __shared__ u64 ek[COLCAP];
    __shared__ unsigned s_nc;
    __shared__ u64 s_top[TOPK];
    __shared__ u64 red[8];
    __shared__ u64 bc;

    const int g = blockIdx.x, tid = threadIdx.x;
    const int b = g >> 2, c = g & 3;
    const int w = (c + 3) & 3;                 // position in visit order [1,2,3,0]
    float* crd = out;                           // coords [B][128][3]
    const bool has_lab = out_size >= B * N_OUT * 4;
    float* lab = out + (out_size - B * N_OUT); // labels [B][128] at tail

    int cnt = (int)g_cnt[g];
    int m = cnt > CAP ? CAP : cnt;
    int k = cnt < NPTS ? cnt : NPTS; if (k > m) k = m;
    int off = 0;
    for (int o = 0; o < w; o++) {
        int t = (int)g_cnt[b * CLS + ((o + 1) & 3)];
        off += t < NPTS ? t : NPTS;
    }
    if (w == 3) {                              // last class fills padding tail
        int tot = off + k;
        for (int i = tot + tid; i < N_OUT; i += 256) {
            if (has_lab) lab[b * N_OUT + i] = -1.0f;
            crd[(b * N_OUT + i) * 3 + 0] = 0.0f;
            crd[(b * N_OUT + i) * 3 + 1] = 0.0f;
            crd[(b * N_OUT + i) * 3 + 2] = 0.0f;
        }
    }

    const unsigned target = (unsigned)(m < TOPK ? m : TOPK);

    // bin geometry from this class's cut (edge is always a multiple of 2^shift)
    unsigned edge = __float_as_uint(g_cut[g]) - 0x3F800000u;       // <= 2^23
    int shift = 0;
    while ((edge >> shift) > 256u) shift++;
    const int sshift = shift > 8 ? shift - 8 : 0;

    // ---- single global sweep: stage to shared + level-1 histogram ----
    hist[tid] = 0u;
    if (tid == 0) { s_nc = 0u; sF = 255u; sBelow = 0u; sF2 = 255u; sB2 = 0u; }
    __syncthreads();
    for (int i = tid; i < m; i += 256) {
        u64 key = g_surv[g][i];
        if (i < SHSTAGE) sk[i] = key;
        unsigned d = (unsigned)((key >> 21) - 0x3F800000u);
        atomicAdd(&hist[d >> shift], 1u);
    }
    __syncthreads();
    hist_cross(hist, 0u, target, wsum, &sF, &sBelow, tid);
    const int F = (int)sF;
    const unsigned nc1 = sBelow + hist[F];

    if (nc1 <= (unsigned)COLCAP) {
        // ---- common path: collect bin <= F from shared ----
        for (int i = tid; i < m; i += 256) {
            u64 key = (i < SHSTAGE) ? sk[i] : g_surv[g][i];
            unsigned d = (unsigned)((key >> 21) - 0x3F800000u);
            if ((int)(d >> shift) <= F)
                coll[atomicAdd(&s_nc, 1u)] = key;
        }
    } else {
        // ---- rare: level-2 refine of boundary bin (parallel crossing) ----
        shist[tid] = 0u;
        __syncthreads();
        for (int i = tid; i < m; i += 256) {
            u64 key = (i < SHSTAGE) ? sk[i] : g_surv[g][i];
            unsigned d = (unsigned)((key >> 21) - 0x3F800000u);
            if ((int)(d >> shift) == F)
                atomicAdd(&shist[(d - ((unsigned)F << shift)) >> sshift], 1u);
        }
        __syncthreads();
        hist_cross(shist, sBelow, target, wsum, &sF2, &sB2, tid);
        const int F2 = (int)sF2;
        for (int i = tid; i < m; i += 256) {
            u64 key = (i < SHSTAGE) ? sk[i] : g_surv[g][i];
            unsigned d = (unsigned)((key >> 21) - 0x3F800000u);
            int bin = (int)(d >> shift);
            bool take = bin < F ||
                        (bin == F && (int)((d - ((unsigned)F << shift)) >> sshift) <= F2);
            if (take) {
                unsigned pos = atomicAdd(&s_nc, 1u);
                if (pos < (unsigned)COLCAP) coll[pos] = key;
            }
        }
    }
    __syncthreads();
    const unsigned nc = s_nc;

    const float* base = logits + (size_t)b * CLS * SVOX;

    if (nc <= (unsigned)COLCAP) {
        // ---- parallel exact keys (one double-exp chain per thread) ----
        ek[tid] = (tid < (int)nc) ? dkey(coll[tid], base) : ~0ull;
        __syncthreads();

        // ---- O(n^2) rank selection (keys unique), fully parallel output --
        if (tid < (int)nc) {
            u64 mine = ek[tid];
            int rank = 0;
            for (int j = 0; j < (int)nc; j++) rank += (ek[j] < mine);
            if (rank < k) {
                int idx  = (int)(mine & 0x1FFFFFull);
                int slot = off + rank;
                if (has_lab) lab[b * N_OUT + slot] = (float)c;
                crd[(b * N_OUT + slot) * 3 + 0] = (float)(idx >> 14);
                crd[(b * N_OUT + slot) * 3 + 1] = (float)((idx >> 7) & 127);
                crd[(b * N_OUT + slot) * 3 + 2] = (float)(idx & 127);
            }
        }
    } else {
        // ---- ultimate fallback (massive f32-key ties): serial extraction --
        u64 prev = 0; int found = 0;
        for (int r = 0; r < TOPK; r++) {
            u64 loc = ~0ull;
            for (int i = tid; i < m; i += 256) {
                u64 kk = (i < SHSTAGE) ? sk[i] : g_surv[g][i];
                if (kk > prev && kk < loc) loc = kk;
            }
            for (int o = 16; o; o >>= 1) {
                u64 t = __shfl_xor_sync(FULLMASK, loc, o);
                if (t < loc) loc = t;
            }
            if ((tid & 31) == 0) red[tid >> 5] = loc;
            __syncthreads();
            if (tid == 0) {
                u64 mn = red[0];
                for (int j = 1; j < 8; j++) if (red[j] < mn) mn = red[j];
                bc = mn; s_top[r] = mn;
            }
            __syncthreads();
            prev = bc;
            __syncthreads();
            if (prev == ~0ull) break;
            found = r + 1;
        }
        if (tid == 0)
            for (int r = found; r < TOPK; r++) s_top[r] = ~0ull;
        __syncthreads();

        if (tid < 32) {
            u64 k0 = dkey(s_top[tid], base);
            u64 k1 = (tid < 16) ? dkey(s_top[32 + tid], base) : ~0ull;
            for (int r = 0; r < k; r++) {
                u64 mn = k0 < k1 ? k0 : k1;
                for (int o = 16; o; o >>= 1) {
                    u64 t = __shfl_xor_sync(FULLMASK, mn, o);
                    if (t < mn) mn = t;
                }
                if (mn == ~0ull) break;
                if (k0 == mn) k0 = ~0ull; else if (k1 == mn) k1 = ~0ull;
                if (tid == 0) {
                    int idx  = (int)(mn & 0x1FFFFFull);
                    int slot = off + r;
                    if (has_lab) lab[b * N_OUT + slot] = (float)c;
                    crd[(b * N_OUT + slot) * 3 + 0] = (float)(idx >> 14);
                    crd[(b * N_OUT + slot) * 3 + 1] = (float)((idx >> 7) & 127);
                    crd[(b * N_OUT + slot) * 3 + 2] = (float)(idx & 127);
                }
            }
        }
    }

    // reset sample counter for the next replay (g_cnt is reset by cutoff)
    if (tid == 0) g_scnt[g] = 0u;
}

// ---------------- launch (kernel launches ONLY) ---------------------------
extern "C" void kernel_launch(void* const* d_in, const int* in_sizes, int n_in,
                              void* d_out, int out_size) {
    const long long want = (long long)B * CLS * SVOX;   // 16,777,216
    int li = 0;
    for (int i = 0; i < n_in; i++)
        if ((long long)in_sizes[i] == want) { li = i; break; }
    if ((long long)in_sizes[li] != want)
        for (int i = 1; i < n_in; i++)
            if (in_sizes[i] > in_sizes[li]) li = i;

    const float* logits = (const float*)d_in[li];
    float* out = (float*)d_out;

    sample_kernel<<<dim3(SVOX / 8192, B), 128>>>(logits);
    cutoff_kernel<<<B * CLS, 256>>>();
    scan_kernel<<<B * (SVOX / 2048), 256>>>(logits);
    final_kernel<<<B * CLS, 256>>>(logits, out, out_size);
}